// round 1
// baseline (speedup 1.0000x reference)
#include <cuda_runtime.h>
#include <math.h>

#define Bn 512
#define Cn 256
#define Ln 196
#define Dn 512
#define SST 200      // padded smem row stride for the SAM tile (conflict-free)
#define PANEL 28     // attn rows staged per panel in k_weighted

// ---- scratch (static device memory; no allocations anywhere) ----
static __device__ float g_simw[Bn * Ln];
static __device__ float g_P[Bn * Ln];
static __device__ float g_Q[Bn * Ln];
static __device__ float g_attn[(size_t)Bn * Ln * Ln];   // ~78.7 MB

// ============================================================================
// K1: similarity weights  simw[b][l] = cross(b) * sigmoid(imf_n . W_sim[l] + b_sim[l]) / 10
// ============================================================================
__global__ __launch_bounds__(256) void k_simw(
    const float* __restrict__ imf, const float* __restrict__ txt,
    const float* __restrict__ Wsim, const float* __restrict__ bsim)
{
    __shared__ float s_im[Dn];
    __shared__ float red[3][8];
    int b = blockIdx.x, t = threadIdx.x, w = t >> 5, ln = t & 31;

    const float* ib = imf + (size_t)b * Dn;
    const float* tb = txt + (size_t)b * Dn;
    float a0 = ib[t], a1 = ib[t + 256];
    float c0 = tb[t], c1 = tb[t + 256];

    float ni = a0 * a0 + a1 * a1;
    float nt = c0 * c0 + c1 * c1;
    float ct = a0 * c0 + a1 * c1;
    #pragma unroll
    for (int o = 16; o > 0; o >>= 1) {
        ni += __shfl_xor_sync(0xffffffffu, ni, o);
        nt += __shfl_xor_sync(0xffffffffu, nt, o);
        ct += __shfl_xor_sync(0xffffffffu, ct, o);
    }
    if (ln == 0) { red[0][w] = ni; red[1][w] = nt; red[2][w] = ct; }
    __syncthreads();
    float nI = 0.f, nT = 0.f, cT = 0.f;
    #pragma unroll
    for (int j = 0; j < 8; j++) { nI += red[0][j]; nT += red[1][j]; cT += red[2][j]; }

    float invI = 1.0f / fmaxf(sqrtf(nI), 1e-12f);
    float invT = 1.0f / fmaxf(sqrtf(nT), 1e-12f);
    float cross = cT * invI * invT;

    s_im[t] = a0 * invI;
    s_im[t + 256] = a1 * invI;
    __syncthreads();

    if (t < Ln) {
        const float4* w4 = reinterpret_cast<const float4*>(Wsim + (size_t)t * Dn);
        const float4* s4 = reinterpret_cast<const float4*>(s_im);
        float acc = 0.f;
        #pragma unroll 8
        for (int d = 0; d < Dn / 4; d++) {
            float4 wv = w4[d], sv = s4[d];
            acc += wv.x * sv.x + wv.y * sv.y + wv.z * sv.z + wv.w * sv.w;
        }
        acc += bsim[t];
        float sg = 1.0f / (1.0f + __expf(-acc));
        g_simw[b * Ln + t] = cross * sg * 0.1f;
    }
}

// ============================================================================
// K2: per-batch  attn = softmax( (samⁿᵀ samⁿ) / 16 )  rows; written row-major
//     one CTA per batch; SAM tile resident in smem; warp tile = 4 rows x 224 cols
// ============================================================================
__global__ __launch_bounds__(256, 1) void k_attn(const float* __restrict__ sam)
{
    extern __shared__ float sS[];           // Cn x SST
    __shared__ float s_inv[Ln];
    int b = blockIdx.x, t = threadIdx.x, w = t >> 5, ln = t & 31;

    const float* Sb = sam + (size_t)b * Cn * Ln;

    // load SAM tile (vectorized, 49 float4 per row)
    for (int c = w; c < Cn; c += 8) {
        const float4* src = reinterpret_cast<const float4*>(Sb + c * Ln);
        float4* dst = reinterpret_cast<float4*>(sS + c * SST);
        for (int j = ln; j < Ln / 4; j += 32) dst[j] = src[j];
    }
    __syncthreads();

    // column inverse L2 norms
    if (t < Ln) {
        float acc = 0.f;
        #pragma unroll 4
        for (int c = 0; c < Cn; c++) { float v = sS[c * SST + t]; acc += v * v; }
        s_inv[t] = 1.0f / fmaxf(sqrtf(acc), 1e-12f);
    }
    __syncthreads();

    // scale columns in place -> sam_norm
    for (int c = w; c < Cn; c += 8)
        for (int j = ln; j < Ln; j += 32) sS[c * SST + j] *= s_inv[j];
    __syncthreads();

    int mm[7];
    bool mv[7];
    #pragma unroll
    for (int k = 0; k < 7; k++) {
        int m = ln + 32 * k;
        mv[k] = (m < Ln);
        mm[k] = mv[k] ? m : (Ln - 1);
    }
    const float rsC = 0.0625f;   // 1/sqrt(256)

    for (int rg = w; rg < 49; rg += 8) {
        int l0 = rg * 4;
        float acc[4][7];
        #pragma unroll
        for (int i = 0; i < 4; i++)
            #pragma unroll
            for (int k = 0; k < 7; k++) acc[i][k] = 0.f;

        #pragma unroll 4
        for (int c = 0; c < Cn; c++) {
            const float* rp = sS + c * SST;
            float sl[4], sm[7];
            #pragma unroll
            for (int i = 0; i < 4; i++) sl[i] = rp[l0 + i];
            #pragma unroll
            for (int k = 0; k < 7; k++) sm[k] = rp[mm[k]];
            #pragma unroll
            for (int i = 0; i < 4; i++)
                #pragma unroll
                for (int k = 0; k < 7; k++) acc[i][k] = fmaf(sl[i], sm[k], acc[i][k]);
        }

        // softmax each of the 4 rows (row fully within this warp)
        #pragma unroll
        for (int i = 0; i < 4; i++) {
            int l = l0 + i;
            float v[7];
            float mx = -3.0e38f;
            #pragma unroll
            for (int k = 0; k < 7; k++) {
                v[k] = mv[k] ? acc[i][k] * rsC : -3.0e38f;
                mx = fmaxf(mx, v[k]);
            }
            #pragma unroll
            for (int o = 16; o > 0; o >>= 1) mx = fmaxf(mx, __shfl_xor_sync(0xffffffffu, mx, o));
            float sum = 0.f;
            #pragma unroll
            for (int k = 0; k < 7; k++) {
                float e = mv[k] ? __expf(v[k] - mx) : 0.f;
                v[k] = e;
                sum += e;
            }
            #pragma unroll
            for (int o = 16; o > 0; o >>= 1) sum += __shfl_xor_sync(0xffffffffu, sum, o);
            float isum = 1.0f / sum;
            float* arow = g_attn + ((size_t)b * Ln + l) * Ln;
            #pragma unroll
            for (int k = 0; k < 7; k++)
                if (mv[k]) arow[mm[k]] = v[k] * isum;
        }
    }
}

// ============================================================================
// K3: per-batch  y = sam + sam @ attn  -> d_out (temp);  column (channel-LN)
//     stats folded to per-column affine P,Q  (x = 0.5*simw*y; LN over C)
// ============================================================================
__global__ __launch_bounds__(256, 1) void k_weighted(
    const float* __restrict__ sam, float* __restrict__ out)
{
    extern __shared__ float smem[];
    float* sS  = smem;                       // Cn x SST
    float* sA  = smem + Cn * SST;            // PANEL x Ln
    float* cs1 = sA + PANEL * Ln;            // 224
    float* cs2 = cs1 + 224;                  // 224
    int b = blockIdx.x, t = threadIdx.x, w = t >> 5, ln = t & 31;

    const float* Sb = sam + (size_t)b * Cn * Ln;
    const float* Ab = g_attn + (size_t)b * Ln * Ln;

    for (int c = w; c < Cn; c += 8) {
        const float4* src = reinterpret_cast<const float4*>(Sb + c * Ln);
        float4* dst = reinterpret_cast<float4*>(sS + c * SST);
        for (int j = ln; j < Ln / 4; j += 32) dst[j] = src[j];
    }
    if (t < 224) { cs1[t] = 0.f; cs2[t] = 0.f; }

    int mm[7];
    bool mv[7];
    #pragma unroll
    for (int k = 0; k < 7; k++) {
        int m = ln + 32 * k;
        mv[k] = (m < Ln);
        mm[k] = mv[k] ? m : 0;
    }
    float csum[7], csq[7];
    #pragma unroll
    for (int k = 0; k < 7; k++) { csum[k] = 0.f; csq[k] = 0.f; }

    for (int cs_ = 0; cs_ < 8; cs_++) {      // 32 channel rows per super-iter
        int c0 = cs_ * 32 + w * 4;
        float acc[4][7];
        #pragma unroll
        for (int i = 0; i < 4; i++)
            #pragma unroll
            for (int k = 0; k < 7; k++) acc[i][k] = 0.f;

        for (int p = 0; p < Ln / PANEL; p++) {   // 7 panels
            __syncthreads();
            {
                const float4* src = reinterpret_cast<const float4*>(Ab + p * PANEL * Ln);
                float4* dst = reinterpret_cast<float4*>(sA);
                for (int e = t; e < PANEL * Ln / 4; e += 256) dst[e] = src[e];
            }
            __syncthreads();
            #pragma unroll 4
            for (int lr = 0; lr < PANEL; lr++) {
                int l = p * PANEL + lr;
                float al[7], si[4];
                #pragma unroll
                for (int k = 0; k < 7; k++) al[k] = sA[lr * Ln + mm[k]];
                #pragma unroll
                for (int i = 0; i < 4; i++) si[i] = sS[(c0 + i) * SST + l];
                #pragma unroll
                for (int i = 0; i < 4; i++)
                    #pragma unroll
                    for (int k = 0; k < 7; k++) acc[i][k] = fmaf(si[i], al[k], acc[i][k]);
            }
        }

        // epilogue for these 32 rows: y = s + w ; write temp; accumulate column sums
        #pragma unroll
        for (int i = 0; i < 4; i++) {
            int c = c0 + i;
            float* orow = out + ((size_t)b * Cn + c) * Ln;
            #pragma unroll
            for (int k = 0; k < 7; k++) {
                if (mv[k]) {
                    float y = sS[c * SST + mm[k]] + acc[i][k];
                    orow[mm[k]] = y;
                    csum[k] += y;
                    csq[k] += y * y;
                }
            }
        }
    }

    // fold per-warp column partials into smem column sums
    #pragma unroll
    for (int k = 0; k < 7; k++) {
        if (mv[k]) {
            atomicAdd(&cs1[mm[k]], csum[k]);
            atomicAdd(&cs2[mm[k]], csq[k]);
        }
    }
    __syncthreads();

    // per-column affine for channel LayerNorm on x = a*y (a = 0.5*simw)
    if (t < Ln) {
        float a = 0.5f * g_simw[b * Ln + t];
        float S1 = cs1[t], S2 = cs2[t];
        float mu_y  = S1 * (1.0f / Cn);
        float var_y = S2 * (1.0f / Cn) - mu_y * mu_y;
        float inv_s = rsqrtf(a * a * var_y + 1e-5f);
        g_P[b * Ln + t] = a * inv_s;
        g_Q[b * Ln + t] = -a * mu_y * inv_s;
    }
}

// ============================================================================
// K4: spatial standardization, fused: warp per (b,c); xn = y*P+Q;
//     out = (xn - mean_m) / (std_m(ddof=1) + 1e-6)
// ============================================================================
__global__ __launch_bounds__(256) void k_spatial(float* __restrict__ out)
{
    int gw = blockIdx.x * 8 + (threadIdx.x >> 5);   // global (b*Cn + c)
    int ln = threadIdx.x & 31;
    int b = gw / Cn;
    float* row = out + (size_t)gw * Ln;
    const float* Pp = g_P + b * Ln;
    const float* Qp = g_Q + b * Ln;

    float x[7];
    float s1 = 0.f, s2 = 0.f;
    #pragma unroll
    for (int k = 0; k < 7; k++) {
        int m = ln + 32 * k;
        if (m < Ln) {
            float xn = fmaf(row[m], Pp[m], Qp[m]);
            x[k] = xn;
            s1 += xn;
            s2 += xn * xn;
        }
    }
    #pragma unroll
    for (int o = 16; o > 0; o >>= 1) {
        s1 += __shfl_xor_sync(0xffffffffu, s1, o);
        s2 += __shfl_xor_sync(0xffffffffu, s2, o);
    }
    float mean = s1 * (1.0f / Ln);
    float var  = (s2 - (float)Ln * mean * mean) * (1.0f / (Ln - 1));
    float sd   = sqrtf(fmaxf(var, 0.f));
    float inv  = 1.0f / (sd + 1e-6f);
    #pragma unroll
    for (int k = 0; k < 7; k++) {
        int m = ln + 32 * k;
        if (m < Ln) row[m] = (x[k] - mean) * inv;
    }
}

// ============================================================================
extern "C" void kernel_launch(void* const* d_in, const int* in_sizes, int n_in,
                              void* d_out, int out_size)
{
    const float* imf  = (const float*)d_in[0];
    const float* txt  = (const float*)d_in[1];
    const float* sam  = (const float*)d_in[2];
    const float* Wsim = (const float*)d_in[3];
    const float* bsim = (const float*)d_in[4];
    float* out = (float*)d_out;

    const int smem_attn = Cn * SST * (int)sizeof(float);                          // 204800
    const int smem_wgt  = (Cn * SST + PANEL * Ln + 448) * (int)sizeof(float);     // 228544
    cudaFuncSetAttribute(k_attn,     cudaFuncAttributeMaxDynamicSharedMemorySize, smem_attn);
    cudaFuncSetAttribute(k_weighted, cudaFuncAttributeMaxDynamicSharedMemorySize, smem_wgt);

    k_simw<<<Bn, 256>>>(imf, txt, Wsim, bsim);
    k_attn<<<Bn, 256, smem_attn>>>(sam);
    k_weighted<<<Bn, 256, smem_wgt>>>(sam, out);
    k_spatial<<<(Bn * Cn) / 8, 256>>>(out);
}

// round 2
// speedup vs baseline: 1.0003x; 1.0003x over previous
#include <cuda_runtime.h>
#include <math.h>

#define Bn 512
#define Cn 256
#define Ln 196
#define Dn 512
#define SST 200      // padded smem row stride for the SAM tile (conflict-free)
#define PANEL 28     // attn rows staged per panel in k_weighted

// ---- scratch (static device memory; no allocations anywhere) ----
static __device__ float g_simw[Bn * Ln];
static __device__ float g_P[Bn * Ln];
static __device__ float g_Q[Bn * Ln];
static __device__ float g_attn[(size_t)Bn * Ln * Ln];   // ~78.7 MB

// ============================================================================
// K1: similarity weights  simw[b][l] = cross(b) * sigmoid(imf_n . W_sim[l] + b_sim[l]) / 10
// ============================================================================
__global__ __launch_bounds__(256) void k_simw(
    const float* __restrict__ imf, const float* __restrict__ txt,
    const float* __restrict__ Wsim, const float* __restrict__ bsim)
{
    __shared__ float s_im[Dn];
    __shared__ float red[3][8];
    int b = blockIdx.x, t = threadIdx.x, w = t >> 5, ln = t & 31;

    const float* ib = imf + (size_t)b * Dn;
    const float* tb = txt + (size_t)b * Dn;
    float a0 = ib[t], a1 = ib[t + 256];
    float c0 = tb[t], c1 = tb[t + 256];

    float ni = a0 * a0 + a1 * a1;
    float nt = c0 * c0 + c1 * c1;
    float ct = a0 * c0 + a1 * c1;
    #pragma unroll
    for (int o = 16; o > 0; o >>= 1) {
        ni += __shfl_xor_sync(0xffffffffu, ni, o);
        nt += __shfl_xor_sync(0xffffffffu, nt, o);
        ct += __shfl_xor_sync(0xffffffffu, ct, o);
    }
    if (ln == 0) { red[0][w] = ni; red[1][w] = nt; red[2][w] = ct; }
    __syncthreads();
    float nI = 0.f, nT = 0.f, cT = 0.f;
    #pragma unroll
    for (int j = 0; j < 8; j++) { nI += red[0][j]; nT += red[1][j]; cT += red[2][j]; }

    float invI = 1.0f / fmaxf(sqrtf(nI), 1e-12f);
    float invT = 1.0f / fmaxf(sqrtf(nT), 1e-12f);
    float cross = cT * invI * invT;

    s_im[t] = a0 * invI;
    s_im[t + 256] = a1 * invI;
    __syncthreads();

    if (t < Ln) {
        const float4* w4 = reinterpret_cast<const float4*>(Wsim + (size_t)t * Dn);
        const float4* s4 = reinterpret_cast<const float4*>(s_im);
        float acc = 0.f;
        #pragma unroll 8
        for (int d = 0; d < Dn / 4; d++) {
            float4 wv = w4[d], sv = s4[d];
            acc += wv.x * sv.x + wv.y * sv.y + wv.z * sv.z + wv.w * sv.w;
        }
        acc += bsim[t];
        float sg = 1.0f / (1.0f + __expf(-acc));
        g_simw[b * Ln + t] = cross * sg * 0.1f;
    }
}

// ============================================================================
// K2: per-batch  attn = softmax( (samⁿᵀ samⁿ) / 16 )  rows; written row-major
//     one CTA per batch; SAM tile resident in smem; warp tile = 4 rows x 224 cols
// ============================================================================
__global__ __launch_bounds__(256, 1) void k_attn(const float* __restrict__ sam)
{
    extern __shared__ float sS[];           // Cn x SST
    __shared__ float s_inv[Ln];
    int b = blockIdx.x, t = threadIdx.x, w = t >> 5, ln = t & 31;

    const float* Sb = sam + (size_t)b * Cn * Ln;

    // load SAM tile (vectorized, 49 float4 per row)
    for (int c = w; c < Cn; c += 8) {
        const float4* src = reinterpret_cast<const float4*>(Sb + c * Ln);
        float4* dst = reinterpret_cast<float4*>(sS + c * SST);
        for (int j = ln; j < Ln / 4; j += 32) dst[j] = src[j];
    }
    __syncthreads();

    // column inverse L2 norms
    if (t < Ln) {
        float acc = 0.f;
        #pragma unroll 4
        for (int c = 0; c < Cn; c++) { float v = sS[c * SST + t]; acc += v * v; }
        s_inv[t] = 1.0f / fmaxf(sqrtf(acc), 1e-12f);
    }
    __syncthreads();

    // scale columns in place -> sam_norm
    for (int c = w; c < Cn; c += 8)
        for (int j = ln; j < Ln; j += 32) sS[c * SST + j] *= s_inv[j];
    __syncthreads();

    int mm[7];
    bool mv[7];
    #pragma unroll
    for (int k = 0; k < 7; k++) {
        int m = ln + 32 * k;
        mv[k] = (m < Ln);
        mm[k] = mv[k] ? m : (Ln - 1);
    }
    const float rsC = 0.0625f;   // 1/sqrt(256)

    for (int rg = w; rg < 49; rg += 8) {
        int l0 = rg * 4;
        float acc[4][7];
        #pragma unroll
        for (int i = 0; i < 4; i++)
            #pragma unroll
            for (int k = 0; k < 7; k++) acc[i][k] = 0.f;

        #pragma unroll 4
        for (int c = 0; c < Cn; c++) {
            const float* rp = sS + c * SST;
            float sl[4], sm[7];
            #pragma unroll
            for (int i = 0; i < 4; i++) sl[i] = rp[l0 + i];
            #pragma unroll
            for (int k = 0; k < 7; k++) sm[k] = rp[mm[k]];
            #pragma unroll
            for (int i = 0; i < 4; i++)
                #pragma unroll
                for (int k = 0; k < 7; k++) acc[i][k] = fmaf(sl[i], sm[k], acc[i][k]);
        }

        // softmax each of the 4 rows (row fully within this warp)
        #pragma unroll
        for (int i = 0; i < 4; i++) {
            int l = l0 + i;
            float v[7];
            float mx = -3.0e38f;
            #pragma unroll
            for (int k = 0; k < 7; k++) {
                v[k] = mv[k] ? acc[i][k] * rsC : -3.0e38f;
                mx = fmaxf(mx, v[k]);
            }
            #pragma unroll
            for (int o = 16; o > 0; o >>= 1) mx = fmaxf(mx, __shfl_xor_sync(0xffffffffu, mx, o));
            float sum = 0.f;
            #pragma unroll
            for (int k = 0; k < 7; k++) {
                float e = mv[k] ? __expf(v[k] - mx) : 0.f;
                v[k] = e;
                sum += e;
            }
            #pragma unroll
            for (int o = 16; o > 0; o >>= 1) sum += __shfl_xor_sync(0xffffffffu, sum, o);
            float isum = 1.0f / sum;
            float* arow = g_attn + ((size_t)b * Ln + l) * Ln;
            #pragma unroll
            for (int k = 0; k < 7; k++)
                if (mv[k]) arow[mm[k]] = v[k] * isum;
        }
    }
}

// ============================================================================
// K3: per-batch  y = sam + sam @ attn  -> d_out (temp);  column (channel-LN)
//     stats folded to per-column affine P,Q  (x = 0.5*simw*y; LN over C)
// ============================================================================
__global__ __launch_bounds__(256, 1) void k_weighted(
    const float* __restrict__ sam, float* __restrict__ out)
{
    extern __shared__ float smem[];
    float* sS  = smem;                       // Cn x SST
    float* sA  = smem + Cn * SST;            // PANEL x Ln
    float* cs1 = sA + PANEL * Ln;            // 224
    float* cs2 = cs1 + 224;                  // 224
    int b = blockIdx.x, t = threadIdx.x, w = t >> 5, ln = t & 31;

    const float* Sb = sam + (size_t)b * Cn * Ln;
    const float* Ab = g_attn + (size_t)b * Ln * Ln;

    for (int c = w; c < Cn; c += 8) {
        const float4* src = reinterpret_cast<const float4*>(Sb + c * Ln);
        float4* dst = reinterpret_cast<float4*>(sS + c * SST);
        for (int j = ln; j < Ln / 4; j += 32) dst[j] = src[j];
    }
    if (t < 224) { cs1[t] = 0.f; cs2[t] = 0.f; }

    int mm[7];
    bool mv[7];
    #pragma unroll
    for (int k = 0; k < 7; k++) {
        int m = ln + 32 * k;
        mv[k] = (m < Ln);
        mm[k] = mv[k] ? m : 0;
    }
    float csum[7], csq[7];
    #pragma unroll
    for (int k = 0; k < 7; k++) { csum[k] = 0.f; csq[k] = 0.f; }

    for (int cs_ = 0; cs_ < 8; cs_++) {      // 32 channel rows per super-iter
        int c0 = cs_ * 32 + w * 4;
        float acc[4][7];
        #pragma unroll
        for (int i = 0; i < 4; i++)
            #pragma unroll
            for (int k = 0; k < 7; k++) acc[i][k] = 0.f;

        for (int p = 0; p < Ln / PANEL; p++) {   // 7 panels
            __syncthreads();
            {
                const float4* src = reinterpret_cast<const float4*>(Ab + p * PANEL * Ln);
                float4* dst = reinterpret_cast<float4*>(sA);
                for (int e = t; e < PANEL * Ln / 4; e += 256) dst[e] = src[e];
            }
            __syncthreads();
            #pragma unroll 4
            for (int lr = 0; lr < PANEL; lr++) {
                int l = p * PANEL + lr;
                float al[7], si[4];
                #pragma unroll
                for (int k = 0; k < 7; k++) al[k] = sA[lr * Ln + mm[k]];
                #pragma unroll
                for (int i = 0; i < 4; i++) si[i] = sS[(c0 + i) * SST + l];
                #pragma unroll
                for (int i = 0; i < 4; i++)
                    #pragma unroll
                    for (int k = 0; k < 7; k++) acc[i][k] = fmaf(si[i], al[k], acc[i][k]);
            }
        }

        // epilogue for these 32 rows: y = s + w ; write temp; accumulate column sums
        #pragma unroll
        for (int i = 0; i < 4; i++) {
            int c = c0 + i;
            float* orow = out + ((size_t)b * Cn + c) * Ln;
            #pragma unroll
            for (int k = 0; k < 7; k++) {
                if (mv[k]) {
                    float y = sS[c * SST + mm[k]] + acc[i][k];
                    orow[mm[k]] = y;
                    csum[k] += y;
                    csq[k] += y * y;
                }
            }
        }
    }

    // fold per-warp column partials into smem column sums
    #pragma unroll
    for (int k = 0; k < 7; k++) {
        if (mv[k]) {
            atomicAdd(&cs1[mm[k]], csum[k]);
            atomicAdd(&cs2[mm[k]], csq[k]);
        }
    }
    __syncthreads();

    // per-column affine for channel LayerNorm on x = a*y (a = 0.5*simw)
    if (t < Ln) {
        float a = 0.5f * g_simw[b * Ln + t];
        float S1 = cs1[t], S2 = cs2[t];
        float mu_y  = S1 * (1.0f / Cn);
        float var_y = S2 * (1.0f / Cn) - mu_y * mu_y;
        float inv_s = rsqrtf(a * a * var_y + 1e-5f);
        g_P[b * Ln + t] = a * inv_s;
        g_Q[b * Ln + t] = -a * mu_y * inv_s;
    }
}

// ============================================================================
// K4: spatial standardization, fused: warp per (b,c); xn = y*P+Q;
//     out = (xn - mean_m) / (std_m(ddof=1) + 1e-6)
// ============================================================================
__global__ __launch_bounds__(256) void k_spatial(float* __restrict__ out)
{
    int gw = blockIdx.x * 8 + (threadIdx.x >> 5);   // global (b*Cn + c)
    int ln = threadIdx.x & 31;
    int b = gw / Cn;
    float* row = out + (size_t)gw * Ln;
    const float* Pp = g_P + b * Ln;
    const float* Qp = g_Q + b * Ln;

    float x[7];
    float s1 = 0.f, s2 = 0.f;
    #pragma unroll
    for (int k = 0; k < 7; k++) {
        int m = ln + 32 * k;
        if (m < Ln) {
            float xn = fmaf(row[m], Pp[m], Qp[m]);
            x[k] = xn;
            s1 += xn;
            s2 += xn * xn;
        }
    }
    #pragma unroll
    for (int o = 16; o > 0; o >>= 1) {
        s1 += __shfl_xor_sync(0xffffffffu, s1, o);
        s2 += __shfl_xor_sync(0xffffffffu, s2, o);
    }
    float mean = s1 * (1.0f / Ln);
    float var  = (s2 - (float)Ln * mean * mean) * (1.0f / (Ln - 1));
    float sd   = sqrtf(fmaxf(var, 0.f));
    float inv  = 1.0f / (sd + 1e-6f);
    #pragma unroll
    for (int k = 0; k < 7; k++) {
        int m = ln + 32 * k;
        if (m < Ln) row[m] = (x[k] - mean) * inv;
    }
}

// ============================================================================
extern "C" void kernel_launch(void* const* d_in, const int* in_sizes, int n_in,
                              void* d_out, int out_size)
{
    const float* imf  = (const float*)d_in[0];
    const float* txt  = (const float*)d_in[1];
    const float* sam  = (const float*)d_in[2];
    const float* Wsim = (const float*)d_in[3];
    const float* bsim = (const float*)d_in[4];
    float* out = (float*)d_out;

    const int smem_attn = Cn * SST * (int)sizeof(float);                          // 204800
    const int smem_wgt  = (Cn * SST + PANEL * Ln + 448) * (int)sizeof(float);     // 228544
    cudaFuncSetAttribute(k_attn,     cudaFuncAttributeMaxDynamicSharedMemorySize, smem_attn);
    cudaFuncSetAttribute(k_weighted, cudaFuncAttributeMaxDynamicSharedMemorySize, smem_wgt);

    k_simw<<<Bn, 256>>>(imf, txt, Wsim, bsim);
    k_attn<<<Bn, 256, smem_attn>>>(sam);
    k_weighted<<<Bn, 256, smem_wgt>>>(sam, out);
    k_spatial<<<(Bn * Cn) / 8, 256>>>(out);
}

// round 3
// speedup vs baseline: 1.4646x; 1.4642x over previous
#include <cuda_runtime.h>
#include <math.h>

#define Bn 512
#define Cn 256
#define Ln 196
#define Dn 512
#define SST 200      // padded smem row stride for the SAM tile (conflict-free)
#define PANEL 28     // attn rows staged per panel in k_weighted

// ---- scratch (static device memory; no allocations anywhere) ----
static __device__ float g_simw[Bn * Ln];
static __device__ float g_attn[(size_t)Bn * Ln * Ln];   // ~78.7 MB

// ============================================================================
// K1: similarity weights  simw[b][l] = cross(b) * sigmoid(imf_n . W_sim[l] + b_sim[l]) / 10
// ============================================================================
__global__ __launch_bounds__(256) void k_simw(
    const float* __restrict__ imf, const float* __restrict__ txt,
    const float* __restrict__ Wsim, const float* __restrict__ bsim)
{
    __shared__ float s_im[Dn];
    __shared__ float red[3][8];
    int b = blockIdx.x, t = threadIdx.x, w = t >> 5, ln = t & 31;

    const float* ib = imf + (size_t)b * Dn;
    const float* tb = txt + (size_t)b * Dn;
    float a0 = ib[t], a1 = ib[t + 256];
    float c0 = tb[t], c1 = tb[t + 256];

    float ni = a0 * a0 + a1 * a1;
    float nt = c0 * c0 + c1 * c1;
    float ct = a0 * c0 + a1 * c1;
    #pragma unroll
    for (int o = 16; o > 0; o >>= 1) {
        ni += __shfl_xor_sync(0xffffffffu, ni, o);
        nt += __shfl_xor_sync(0xffffffffu, nt, o);
        ct += __shfl_xor_sync(0xffffffffu, ct, o);
    }
    if (ln == 0) { red[0][w] = ni; red[1][w] = nt; red[2][w] = ct; }
    __syncthreads();
    float nI = 0.f, nT = 0.f, cT = 0.f;
    #pragma unroll
    for (int j = 0; j < 8; j++) { nI += red[0][j]; nT += red[1][j]; cT += red[2][j]; }

    float invI = 1.0f / fmaxf(sqrtf(nI), 1e-12f);
    float invT = 1.0f / fmaxf(sqrtf(nT), 1e-12f);
    float cross = cT * invI * invT;

    s_im[t] = a0 * invI;
    s_im[t + 256] = a1 * invI;
    __syncthreads();

    if (t < Ln) {
        const float4* w4 = reinterpret_cast<const float4*>(Wsim + (size_t)t * Dn);
        const float4* s4 = reinterpret_cast<const float4*>(s_im);
        float acc = 0.f;
        #pragma unroll 8
        for (int d = 0; d < Dn / 4; d++) {
            float4 wv = w4[d], sv = s4[d];
            acc += wv.x * sv.x + wv.y * sv.y + wv.z * sv.z + wv.w * sv.w;
        }
        acc += bsim[t];
        float sg = 1.0f / (1.0f + __expf(-acc));
        g_simw[b * Ln + t] = cross * sg * 0.1f;
    }
}

// ============================================================================
// K2: per-batch  attn = softmax( (sam_n^T sam_n) / 16 )  -> g_attn row-major
//     one CTA/batch, 512 threads (16 warps), warp tile = 4 rows x 224 cols
// ============================================================================
__global__ __launch_bounds__(512, 1) void k_attn(const float* __restrict__ sam)
{
    extern __shared__ float sS[];           // Cn x SST
    __shared__ float s_inv[Ln];
    int b = blockIdx.x, t = threadIdx.x, w = t >> 5, ln = t & 31;

    const float* Sb = sam + (size_t)b * Cn * Ln;

    // load SAM tile (49 float4 per row)
    for (int c = w; c < Cn; c += 16) {
        const float4* src = reinterpret_cast<const float4*>(Sb + c * Ln);
        float4* dst = reinterpret_cast<float4*>(sS + c * SST);
        for (int j = ln; j < Ln / 4; j += 32) dst[j] = src[j];
    }
    __syncthreads();

    // column inverse L2 norms
    if (t < Ln) {
        float acc = 0.f;
        #pragma unroll 4
        for (int c = 0; c < Cn; c++) { float v = sS[c * SST + t]; acc += v * v; }
        s_inv[t] = 1.0f / fmaxf(sqrtf(acc), 1e-12f);
    }
    __syncthreads();

    // scale columns in place -> sam_norm
    for (int c = w; c < Cn; c += 16)
        for (int j = ln; j < Ln; j += 32) sS[c * SST + j] *= s_inv[j];
    __syncthreads();

    int mm[7];
    bool mv[7];
    #pragma unroll
    for (int k = 0; k < 7; k++) {
        int m = ln + 32 * k;
        mv[k] = (m < Ln);
        mm[k] = mv[k] ? m : (Ln - 1);
    }
    const float rsC = 0.0625f;   // 1/sqrt(256)

    for (int rg = w; rg < 49; rg += 16) {
        int l0 = rg * 4;
        float acc[4][7];
        #pragma unroll
        for (int i = 0; i < 4; i++)
            #pragma unroll
            for (int k = 0; k < 7; k++) acc[i][k] = 0.f;

        #pragma unroll 4
        for (int c = 0; c < Cn; c++) {
            const float* rp = sS + c * SST;
            float4 sl4 = *reinterpret_cast<const float4*>(rp + l0);  // LDS.128 broadcast
            float sl[4] = { sl4.x, sl4.y, sl4.z, sl4.w };
            float sm[7];
            #pragma unroll
            for (int k = 0; k < 7; k++) sm[k] = rp[mm[k]];
            #pragma unroll
            for (int i = 0; i < 4; i++)
                #pragma unroll
                for (int k = 0; k < 7; k++) acc[i][k] = fmaf(sl[i], sm[k], acc[i][k]);
        }

        // softmax each of the 4 rows (row fully within this warp)
        #pragma unroll
        for (int i = 0; i < 4; i++) {
            int l = l0 + i;
            float v[7];
            float mx = -3.0e38f;
            #pragma unroll
            for (int k = 0; k < 7; k++) {
                v[k] = mv[k] ? acc[i][k] * rsC : -3.0e38f;
                mx = fmaxf(mx, v[k]);
            }
            #pragma unroll
            for (int o = 16; o > 0; o >>= 1) mx = fmaxf(mx, __shfl_xor_sync(0xffffffffu, mx, o));
            float sum = 0.f;
            #pragma unroll
            for (int k = 0; k < 7; k++) {
                float e = mv[k] ? __expf(v[k] - mx) : 0.f;
                v[k] = e;
                sum += e;
            }
            #pragma unroll
            for (int o = 16; o > 0; o >>= 1) sum += __shfl_xor_sync(0xffffffffu, sum, o);
            float isum = 1.0f / sum;
            float* arow = g_attn + ((size_t)b * Ln + l) * Ln;
            #pragma unroll
            for (int k = 0; k < 7; k++)
                if (mv[k]) arow[mm[k]] = v[k] * isum;
        }
    }
}

// ============================================================================
// K3 (fully fused): per-batch  y = sam + sam @ attn  (kept in smem);
//   channel-LN folded to per-column affine P,Q;  spatial standardization;
//   single write of d_out. 512 threads, one CTA per batch.
// ============================================================================
__global__ __launch_bounds__(512, 1) void k_weighted(
    const float* __restrict__ sam, float* __restrict__ out)
{
    extern __shared__ float smem[];
    float* sS  = smem;                       // Cn x SST  (sam, later y)
    float* sA  = smem + Cn * SST;            // PANEL x Ln
    float* cs1 = sA + PANEL * Ln;            // 224  (col sums -> P)
    float* cs2 = cs1 + 224;                  // 224  (col sumsq -> Q)
    int b = blockIdx.x, t = threadIdx.x, w = t >> 5, ln = t & 31;

    const float* Sb = sam + (size_t)b * Cn * Ln;
    const float* Ab = g_attn + (size_t)b * Ln * Ln;

    for (int c = w; c < Cn; c += 16) {
        const float4* src = reinterpret_cast<const float4*>(Sb + c * Ln);
        float4* dst = reinterpret_cast<float4*>(sS + c * SST);
        for (int j = ln; j < Ln / 4; j += 32) dst[j] = src[j];
    }
    if (t < 448) cs1[t] = 0.f;    // zeros cs1 and cs2 (contiguous)

    int mm[7];
    bool mv[7];
    #pragma unroll
    for (int k = 0; k < 7; k++) {
        int m = ln + 32 * k;
        mv[k] = (m < Ln);
        mm[k] = mv[k] ? m : 0;
    }
    float csum[7], csq[7];
    #pragma unroll
    for (int k = 0; k < 7; k++) { csum[k] = 0.f; csq[k] = 0.f; }

    for (int cs_ = 0; cs_ < 4; cs_++) {      // 64 channel rows per super-iter
        int c0 = cs_ * 64 + w * 4;
        float acc[4][7];
        #pragma unroll
        for (int i = 0; i < 4; i++)
            #pragma unroll
            for (int k = 0; k < 7; k++) acc[i][k] = 0.f;

        for (int p = 0; p < Ln / PANEL; p++) {   // 7 panels of 28 attn rows
            __syncthreads();
            {
                const float4* src = reinterpret_cast<const float4*>(Ab + p * PANEL * Ln);
                float4* dst = reinterpret_cast<float4*>(sA);
                for (int e = t; e < PANEL * Ln / 4; e += 512) dst[e] = src[e];
            }
            __syncthreads();
            #pragma unroll
            for (int lc = 0; lc < PANEL / 4; lc++) {
                int lb = p * PANEL + lc * 4;
                float4 si4[4];
                #pragma unroll
                for (int i = 0; i < 4; i++)
                    si4[i] = *reinterpret_cast<const float4*>(sS + (c0 + i) * SST + lb);
                const float* sif = reinterpret_cast<const float*>(si4);
                #pragma unroll
                for (int j = 0; j < 4; j++) {
                    int lr = lc * 4 + j;
                    float al[7];
                    #pragma unroll
                    for (int k = 0; k < 7; k++) al[k] = sA[lr * Ln + mm[k]];
                    #pragma unroll
                    for (int i = 0; i < 4; i++)
                        #pragma unroll
                        for (int k = 0; k < 7; k++)
                            acc[i][k] = fmaf(sif[i * 4 + j], al[k], acc[i][k]);
                }
            }
        }

        // epilogue: y = sam + weighted, overwrite own sS rows, gather col stats
        #pragma unroll
        for (int i = 0; i < 4; i++) {
            float* srow = sS + (c0 + i) * SST;
            #pragma unroll
            for (int k = 0; k < 7; k++) {
                if (mv[k]) {
                    float y = srow[mm[k]] + acc[i][k];
                    srow[mm[k]] = y;
                    csum[k] += y;
                    csq[k] += y * y;
                }
            }
        }
    }

    // fold per-warp column partials
    #pragma unroll
    for (int k = 0; k < 7; k++) {
        if (mv[k]) {
            atomicAdd(&cs1[mm[k]], csum[k]);
            atomicAdd(&cs2[mm[k]], csq[k]);
        }
    }
    __syncthreads();

    // per-column affine for channel LayerNorm on x = a*y (a = 0.5*simw)
    if (t < Ln) {
        float a = 0.5f * g_simw[b * Ln + t];
        float S1 = cs1[t], S2 = cs2[t];
        float mu_y  = S1 * (1.0f / Cn);
        float var_y = S2 * (1.0f / Cn) - mu_y * mu_y;
        float inv_s = rsqrtf(a * a * var_y + 1e-5f);
        cs1[t] = a * inv_s;               // P
        cs2[t] = -a * mu_y * inv_s;       // Q
    }
    __syncthreads();

    // fused spatial standardization: xn = y*P+Q; out = (xn - mean)/(std(ddof=1)+1e-6)
    const float4* P4 = reinterpret_cast<const float4*>(cs1);
    const float4* Q4 = reinterpret_cast<const float4*>(cs2);
    bool has2 = (ln + 32) < Ln / 4;       // lanes 0..16 own a second float4 group
    int g2 = has2 ? (ln + 32) : 0;
    float4 p0 = P4[ln], q0 = Q4[ln];
    float4 p1 = P4[g2], q1 = Q4[g2];

    for (int c = w; c < Cn; c += 16) {
        const float4* yrow = reinterpret_cast<const float4*>(sS + c * SST);
        float4 y0 = yrow[ln];
        float x0[4] = { fmaf(y0.x, p0.x, q0.x), fmaf(y0.y, p0.y, q0.y),
                        fmaf(y0.z, p0.z, q0.z), fmaf(y0.w, p0.w, q0.w) };
        float x1[4] = { 0.f, 0.f, 0.f, 0.f };
        if (has2) {
            float4 y1 = yrow[g2];
            x1[0] = fmaf(y1.x, p1.x, q1.x); x1[1] = fmaf(y1.y, p1.y, q1.y);
            x1[2] = fmaf(y1.z, p1.z, q1.z); x1[3] = fmaf(y1.w, p1.w, q1.w);
        }
        float s1 = x0[0] + x0[1] + x0[2] + x0[3];
        float s2 = x0[0]*x0[0] + x0[1]*x0[1] + x0[2]*x0[2] + x0[3]*x0[3];
        if (has2) {
            s1 += x1[0] + x1[1] + x1[2] + x1[3];
            s2 += x1[0]*x1[0] + x1[1]*x1[1] + x1[2]*x1[2] + x1[3]*x1[3];
        }
        #pragma unroll
        for (int o = 16; o > 0; o >>= 1) {
            s1 += __shfl_xor_sync(0xffffffffu, s1, o);
            s2 += __shfl_xor_sync(0xffffffffu, s2, o);
        }
        float mean = s1 * (1.0f / Ln);
        float var  = (s2 - (float)Ln * mean * mean) * (1.0f / (Ln - 1));
        float sd   = sqrtf(fmaxf(var, 0.f));
        float inv  = 1.0f / (sd + 1e-6f);

        float4* orow = reinterpret_cast<float4*>(out + ((size_t)b * Cn + c) * Ln);
        float4 o0 = { (x0[0]-mean)*inv, (x0[1]-mean)*inv, (x0[2]-mean)*inv, (x0[3]-mean)*inv };
        orow[ln] = o0;
        if (has2) {
            float4 o1 = { (x1[0]-mean)*inv, (x1[1]-mean)*inv, (x1[2]-mean)*inv, (x1[3]-mean)*inv };
            orow[g2] = o1;
        }
    }
}

// ============================================================================
extern "C" void kernel_launch(void* const* d_in, const int* in_sizes, int n_in,
                              void* d_out, int out_size)
{
    const float* imf  = (const float*)d_in[0];
    const float* txt  = (const float*)d_in[1];
    const float* sam  = (const float*)d_in[2];
    const float* Wsim = (const float*)d_in[3];
    const float* bsim = (const float*)d_in[4];
    float* out = (float*)d_out;

    const int smem_attn = Cn * SST * (int)sizeof(float);                          // 204800
    const int smem_wgt  = (Cn * SST + PANEL * Ln + 448) * (int)sizeof(float);     // 228544
    cudaFuncSetAttribute(k_attn,     cudaFuncAttributeMaxDynamicSharedMemorySize, smem_attn);
    cudaFuncSetAttribute(k_weighted, cudaFuncAttributeMaxDynamicSharedMemorySize, smem_wgt);

    k_simw<<<Bn, 256>>>(imf, txt, Wsim, bsim);
    k_attn<<<Bn, 512, smem_attn>>>(sam);
    k_weighted<<<Bn, 512, smem_wgt>>>(sam, out);
}

// round 5
// speedup vs baseline: 2.9467x; 2.0120x over previous
#include <cuda_runtime.h>
#include <math.h>
#include <stdint.h>

#define Bn 512
#define Cn 256
#define Ln 196
#define Dn 512
#define XST 260      // Xt stride (floats), 260 mod 32 = 4  -> conflict-free frags
#define AST 108      // A_sm stride, 108 mod 32 = 12        -> conflict-free
#define BST 200      // B_sm stride, 200 mod 32 = 8         -> conflict-free
#define KP  104      // k-panel size (13 mma k-steps)

// ---- scratch ----
static __device__ float g_simw[Bn * Ln];
static __device__ float g_P[Bn * Ln];
static __device__ float g_Q[Bn * Ln];
static __device__ float g_attn[(size_t)Bn * Ln * Ln];   // attn[b][l][m], row-major

// ============================ helpers ============================
__device__ __forceinline__ uint32_t f2tf(float f) {
    uint32_t r;
    asm("cvt.rna.tf32.f32 %0, %1;" : "=r"(r) : "f"(f));
    return r;
}
__device__ __forceinline__ uint32_t fu(float f) { return __float_as_uint(f); }

__device__ __forceinline__ void mma8(float* d, const uint32_t* a, const uint32_t* b) {
    asm volatile("mma.sync.aligned.m16n8k8.row.col.f32.tf32.tf32.f32 "
        "{%0,%1,%2,%3}, {%4,%5,%6,%7}, {%8,%9}, {%0,%1,%2,%3};"
        : "+f"(d[0]), "+f"(d[1]), "+f"(d[2]), "+f"(d[3])
        : "r"(a[0]), "r"(a[1]), "r"(a[2]), "r"(a[3]), "r"(b[0]), "r"(b[1]));
}

// ============================================================================
// K1: similarity weights (warp-per-row)
// ============================================================================
__global__ __launch_bounds__(256) void k_simw(
    const float* __restrict__ imf, const float* __restrict__ txt,
    const float* __restrict__ Wsim, const float* __restrict__ bsim)
{
    __shared__ float s_im[Dn];
    __shared__ float red[3][8];
    int b = blockIdx.x, t = threadIdx.x, w = t >> 5, ln = t & 31;

    const float* ib = imf + (size_t)b * Dn;
    const float* tb = txt + (size_t)b * Dn;
    float a0 = ib[t], a1 = ib[t + 256];
    float c0 = tb[t], c1 = tb[t + 256];
    float ni = a0*a0 + a1*a1, nt = c0*c0 + c1*c1, ct = a0*c0 + a1*c1;
    #pragma unroll
    for (int o = 16; o > 0; o >>= 1) {
        ni += __shfl_xor_sync(0xffffffffu, ni, o);
        nt += __shfl_xor_sync(0xffffffffu, nt, o);
        ct += __shfl_xor_sync(0xffffffffu, ct, o);
    }
    if (ln == 0) { red[0][w] = ni; red[1][w] = nt; red[2][w] = ct; }
    __syncthreads();
    float nI = 0.f, nT = 0.f, cT = 0.f;
    #pragma unroll
    for (int j = 0; j < 8; j++) { nI += red[0][j]; nT += red[1][j]; cT += red[2][j]; }
    float invI = 1.0f / fmaxf(sqrtf(nI), 1e-12f);
    float invT = 1.0f / fmaxf(sqrtf(nT), 1e-12f);
    float cross = cT * invI * invT;
    s_im[t] = a0 * invI; s_im[t + 256] = a1 * invI;
    __syncthreads();

    const float4* s4 = reinterpret_cast<const float4*>(s_im);
    for (int r = w; r < Ln; r += 8) {
        const float4* wr = reinterpret_cast<const float4*>(Wsim + (size_t)r * Dn);
        float acc = 0.f;
        #pragma unroll
        for (int i = 0; i < 4; i++) {
            float4 a = wr[ln + i * 32];
            float4 s = s4[ln + i * 32];
            acc += a.x*s.x + a.y*s.y + a.z*s.z + a.w*s.w;
        }
        #pragma unroll
        for (int o = 16; o > 0; o >>= 1) acc += __shfl_xor_sync(0xffffffffu, acc, o);
        if (ln == 0) {
            acc += bsim[r];
            g_simw[b * Ln + r] = cross * (1.0f / (1.0f + __expf(-acc))) * 0.1f;
        }
    }
}

// ============================================================================
// K2: attn = softmax over m of (sam_n^T sam_n / 16) via tf32 mma.sync.
//   Xt[l][c] in smem (stride 260), rows scaled by inv_l * 0.25 (pre-tf32).
//   8 warps; warp owns a 16-row m-tile x 200 cols; full-row softmax in regs.
// ============================================================================
__global__ __launch_bounds__(256, 1) void k_attn(const float* __restrict__ sam)
{
    extern __shared__ float Xt[];   // 208 x XST
    int b = blockIdx.x, t = threadIdx.x, w = t >> 5, ln = t & 31;
    int g = ln >> 2, tig = ln & 3;
    const float* Sb = sam + (size_t)b * Cn * Ln;

    // zero pad rows 196..207
    for (int i = t; i < 12 * XST; i += 256) Xt[196 * XST + i] = 0.f;
    // stage transpose: Xt[l][c] = sam[c][l]
    for (int idx = t; idx < Cn * 49; idx += 256) {
        int c = idx / 49, l4 = idx % 49;
        float4 v = reinterpret_cast<const float4*>(Sb)[idx];
        int l = l4 * 4;
        Xt[(l+0)*XST + c] = v.x; Xt[(l+1)*XST + c] = v.y;
        Xt[(l+2)*XST + c] = v.z; Xt[(l+3)*XST + c] = v.w;
    }
    __syncthreads();

    // row norms (over c), scale by inv/4, convert to tf32 bits in place
    for (int l = w; l < Ln; l += 8) {
        float4* row4 = reinterpret_cast<float4*>(Xt + l * XST);
        float4 v0 = row4[ln], v1 = row4[ln + 32];
        float s = v0.x*v0.x + v0.y*v0.y + v0.z*v0.z + v0.w*v0.w
                + v1.x*v1.x + v1.y*v1.y + v1.z*v1.z + v1.w*v1.w;
        #pragma unroll
        for (int o = 16; o > 0; o >>= 1) s += __shfl_xor_sync(0xffffffffu, s, o);
        float iv = 0.25f / fmaxf(sqrtf(s), 1e-12f);
        float4 o0, o1;
        o0.x = __uint_as_float(f2tf(v0.x * iv)); o0.y = __uint_as_float(f2tf(v0.y * iv));
        o0.z = __uint_as_float(f2tf(v0.z * iv)); o0.w = __uint_as_float(f2tf(v0.w * iv));
        o1.x = __uint_as_float(f2tf(v1.x * iv)); o1.y = __uint_as_float(f2tf(v1.y * iv));
        o1.z = __uint_as_float(f2tf(v1.z * iv)); o1.w = __uint_as_float(f2tf(v1.w * iv));
        row4[ln] = o0; row4[ln + 32] = o1;
    }
    __syncthreads();

    // MMA + softmax: jobs = m-tiles mt in {w, w+8} (13 total)
    for (int mt = w; mt < 13; mt += 8) {
        float acc[25][4];
        #pragma unroll
        for (int n = 0; n < 25; n++)
            #pragma unroll
            for (int j = 0; j < 4; j++) acc[n][j] = 0.f;

        const float* A0 = Xt + (mt * 16 + g) * XST;
        const float* A1 = A0 + 8 * XST;
        for (int ks = 0; ks < 32; ks++) {
            int k0 = ks * 8;
            uint32_t a[4] = { fu(A0[k0 + tig]), fu(A1[k0 + tig]),
                              fu(A0[k0 + tig + 4]), fu(A1[k0 + tig + 4]) };
            #pragma unroll
            for (int n = 0; n < 25; n++) {
                const float* Bp = Xt + (n * 8 + g) * XST + k0 + tig;
                uint32_t bb[2] = { fu(Bp[0]), fu(Bp[4]) };
                mma8(acc[n], a, bb);
            }
        }

        // softmax per row (row fully within the 4-lane quad)
        #pragma unroll
        for (int rh = 0; rh < 2; rh++) {
            int l = mt * 16 + g + 8 * rh;
            float mx = -3.0e38f;
            #pragma unroll
            for (int n = 0; n < 25; n++) {
                int col0 = n * 8 + 2 * tig;
                if (col0 < Ln) {
                    mx = fmaxf(mx, acc[n][rh*2]);
                    mx = fmaxf(mx, acc[n][rh*2+1]);
                }
            }
            mx = fmaxf(mx, __shfl_xor_sync(0xffffffffu, mx, 1));
            mx = fmaxf(mx, __shfl_xor_sync(0xffffffffu, mx, 2));
            float sum = 0.f;
            #pragma unroll
            for (int n = 0; n < 25; n++) {
                int col0 = n * 8 + 2 * tig;
                if (col0 < Ln) {
                    float e0 = __expf(acc[n][rh*2]   - mx);
                    float e1 = __expf(acc[n][rh*2+1] - mx);
                    acc[n][rh*2] = e0; acc[n][rh*2+1] = e1;
                    sum += e0 + e1;
                }
            }
            sum += __shfl_xor_sync(0xffffffffu, sum, 1);
            sum += __shfl_xor_sync(0xffffffffu, sum, 2);
            float is = 1.0f / sum;
            if (l < Ln) {
                float* ar = g_attn + ((size_t)b * Ln + l) * Ln;
                #pragma unroll
                for (int n = 0; n < 25; n++) {
                    int col0 = n * 8 + 2 * tig;
                    if (col0 < Ln)
                        *reinterpret_cast<float2*>(ar + col0) =
                            make_float2(acc[n][rh*2] * is, acc[n][rh*2+1] * is);
                }
            }
        }
    }
}

// ============================================================================
// K3: weighted = sam @ attn via tf32 mma.sync; y = sam + weighted -> out;
//   column stats -> P,Q (channel-LN affine folded with 0.5*simw).
//   8 warps; 2 c-passes x (2 k-panels staged in smem).
// ============================================================================
__global__ __launch_bounds__(256, 1) void k_weighted(
    const float* __restrict__ sam, float* __restrict__ out)
{
    extern __shared__ float dyn[];
    float* A_sm = dyn;                    // 128 x AST
    float* B_sm = dyn + 128 * AST;        // KP x BST
    __shared__ float cs1[196];
    __shared__ float cs2[196];
    int b = blockIdx.x, t = threadIdx.x, w = t >> 5, ln = t & 31;
    int g = ln >> 2, tig = ln & 3;

    const float* Sb = sam + (size_t)b * Cn * Ln;
    const float* At = g_attn + (size_t)b * Ln * Ln;

    if (t < 196) { cs1[t] = 0.f; cs2[t] = 0.f; }

    for (int p = 0; p < 2; p++) {
        float acc[25][4];
        #pragma unroll
        for (int n = 0; n < 25; n++)
            #pragma unroll
            for (int j = 0; j < 4; j++) acc[n][j] = 0.f;

        for (int kh = 0; kh < 2; kh++) {
            __syncthreads();
            // stage A: 128 rows (this pass's c) x 104 cols (tf32)
            for (int idx = t; idx < 128 * 26; idx += 256) {
                int cr = idx / 26, ch = idx % 26;
                int gk = kh * KP + ch * 4;
                float4 v = make_float4(0.f, 0.f, 0.f, 0.f);
                if (gk < Ln) v = *reinterpret_cast<const float4*>(Sb + (size_t)(p*128 + cr) * Ln + gk);
                float* dst = A_sm + cr * AST + ch * 4;
                dst[0] = __uint_as_float(f2tf(v.x)); dst[1] = __uint_as_float(f2tf(v.y));
                dst[2] = __uint_as_float(f2tf(v.z)); dst[3] = __uint_as_float(f2tf(v.w));
            }
            // stage B: 104 k-rows x 200 cols (tf32), pads zero
            for (int idx = t; idx < KP * 50; idx += 256) {
                int kk = idx / 50, ch = idx % 50;
                int l = kh * KP + kk;
                float4 v = make_float4(0.f, 0.f, 0.f, 0.f);
                if (l < Ln && ch < 49) v = *reinterpret_cast<const float4*>(At + (size_t)l * Ln + ch * 4);
                float* dst = B_sm + kk * BST + ch * 4;
                dst[0] = __uint_as_float(f2tf(v.x)); dst[1] = __uint_as_float(f2tf(v.y));
                dst[2] = __uint_as_float(f2tf(v.z)); dst[3] = __uint_as_float(f2tf(v.w));
            }
            __syncthreads();

            int nsteps = kh ? 12 : 13;
            const float* A0 = A_sm + (w * 16 + g) * AST;
            const float* A1 = A0 + 8 * AST;
            for (int ks = 0; ks < nsteps; ks++) {
                int k0 = ks * 8;
                uint32_t a[4] = { fu(A0[k0 + tig]), fu(A1[k0 + tig]),
                                  fu(A0[k0 + tig + 4]), fu(A1[k0 + tig + 4]) };
                #pragma unroll
                for (int n = 0; n < 25; n++) {
                    const float* Bp = B_sm + (k0 + tig) * BST + n * 8 + g;
                    uint32_t bb[2] = { fu(Bp[0]), fu(Bp[4 * BST]) };
                    mma8(acc[n], a, bb);
                }
            }
        }

        // epilogue: y = sam + D -> out; column sums via quad-transposed shuffles
        int c0r = p * 128 + w * 16 + g;
        int c1r = c0r + 8;
        const float* S0 = Sb + (size_t)c0r * Ln;
        const float* S1 = Sb + (size_t)c1r * Ln;
        float* O0 = out + ((size_t)b * Cn + c0r) * Ln;
        float* O1 = out + ((size_t)b * Cn + c1r) * Ln;
        #pragma unroll
        for (int n = 0; n < 25; n++) {
            int col0 = n * 8 + 2 * tig;
            bool v = col0 < Ln;
            float y0 = 0.f, y1 = 0.f, y2 = 0.f, y3 = 0.f;
            if (v) {
                float2 s0 = *reinterpret_cast<const float2*>(S0 + col0);
                float2 s1 = *reinterpret_cast<const float2*>(S1 + col0);
                y0 = s0.x + acc[n][0]; y1 = s0.y + acc[n][1];
                y2 = s1.x + acc[n][2]; y3 = s1.y + acc[n][3];
                *reinterpret_cast<float2*>(O0 + col0) = make_float2(y0, y1);
                *reinterpret_cast<float2*>(O1 + col0) = make_float2(y2, y3);
            }
            float sa0 = y0 + y2, sa1 = y1 + y3;
            float sq0 = y0*y0 + y2*y2, sq1 = y1*y1 + y3*y3;
            #pragma unroll
            for (int o = 4; o < 32; o <<= 1) {
                sa0 += __shfl_xor_sync(0xffffffffu, sa0, o);
                sa1 += __shfl_xor_sync(0xffffffffu, sa1, o);
                sq0 += __shfl_xor_sync(0xffffffffu, sq0, o);
                sq1 += __shfl_xor_sync(0xffffffffu, sq1, o);
            }
            if (g == 0 && v) {
                atomicAdd(&cs1[col0], sa0);     atomicAdd(&cs1[col0 + 1], sa1);
                atomicAdd(&cs2[col0], sq0);     atomicAdd(&cs2[col0 + 1], sq1);
            }
        }
    }
    __syncthreads();

    if (t < Ln) {
        float a = 0.5f * g_simw[b * Ln + t];
        float mu_y  = cs1[t] * (1.0f / Cn);
        float var_y = cs2[t] * (1.0f / Cn) - mu_y * mu_y;
        float inv_s = rsqrtf(a * a * var_y + 1e-5f);
        g_P[b * Ln + t] = a * inv_s;
        g_Q[b * Ln + t] = -a * mu_y * inv_s;
    }
}

// ============================================================================
// K4: spatial standardization (proven R2 kernel)
// ============================================================================
__global__ __launch_bounds__(256) void k_spatial(float* __restrict__ out)
{
    int gw = blockIdx.x * 8 + (threadIdx.x >> 5);
    int ln = threadIdx.x & 31;
    int b = gw / Cn;
    float* row = out + (size_t)gw * Ln;
    const float* Pp = g_P + b * Ln;
    const float* Qp = g_Q + b * Ln;

    float x[7];
    float s1 = 0.f, s2 = 0.f;
    #pragma unroll
    for (int k = 0; k < 7; k++) {
        int m = ln + 32 * k;
        if (m < Ln) {
            float xn = fmaf(row[m], Pp[m], Qp[m]);
            x[k] = xn; s1 += xn; s2 += xn * xn;
        }
    }
    #pragma unroll
    for (int o = 16; o > 0; o >>= 1) {
        s1 += __shfl_xor_sync(0xffffffffu, s1, o);
        s2 += __shfl_xor_sync(0xffffffffu, s2, o);
    }
    float mean = s1 * (1.0f / Ln);
    float var  = (s2 - (float)Ln * mean * mean) * (1.0f / (Ln - 1));
    float inv  = 1.0f / (sqrtf(fmaxf(var, 0.f)) + 1e-6f);
    #pragma unroll
    for (int k = 0; k < 7; k++) {
        int m = ln + 32 * k;
        if (m < Ln) row[m] = (x[k] - mean) * inv;
    }
}

// ============================================================================
extern "C" void kernel_launch(void* const* d_in, const int* in_sizes, int n_in,
                              void* d_out, int out_size)
{
    const float* imf  = (const float*)d_in[0];
    const float* txt  = (const float*)d_in[1];
    const float* sam  = (const float*)d_in[2];
    const float* Wsim = (const float*)d_in[3];
    const float* bsim = (const float*)d_in[4];
    float* out = (float*)d_out;

    const int smem_attn = 208 * XST * (int)sizeof(float);               // 216,320
    const int smem_wgt  = (128 * AST + KP * BST) * (int)sizeof(float);  // 138,496
    cudaFuncSetAttribute(k_attn,     cudaFuncAttributeMaxDynamicSharedMemorySize, smem_attn);
    cudaFuncSetAttribute(k_weighted, cudaFuncAttributeMaxDynamicSharedMemorySize, smem_wgt);

    k_simw<<<Bn, 256>>>(imf, txt, Wsim, bsim);
    k_attn<<<Bn, 256, smem_attn>>>(sam);
    k_weighted<<<Bn, 256, smem_wgt>>>(sam, out);
    k_spatial<<<(Bn * Cn) / 8, 256>>>(out);
}